// round 1
// baseline (speedup 1.0000x reference)
#include <cuda_runtime.h>
#include <math.h>

#define NHW 1024
#define KDIM 256
#define NBT 64

// Scratch (device globals: allocation-guard-safe)
__device__ float g_qkv[(size_t)NBT * 768 * NHW];   // 192 MB
__device__ float g_att[(size_t)NBT * 256 * NHW];   // 64 MB

__device__ __forceinline__ unsigned f2tf(float x) {
    unsigned u;
    asm("cvt.rna.tf32.f32 %0, %1;" : "=r"(u) : "f"(x));
    return u;
}

// C[bt][m][n] = sum_k W[m][k] * X[bt][k][n] + bias[m]
// M in {768, 256}, K = 256, N = 1024 per batch, 64 batches.
template<int M>
__global__ __launch_bounds__(256) void gemm_tf32_kernel(
    const float* __restrict__ W, const float* __restrict__ X,
    const float* __restrict__ bias, float* __restrict__ out)
{
    constexpr int BM = 128, BN = 64, BK = 32;
    __shared__ float As[BK][BM + 1];   // [k][m], pad -> conflict-light
    __shared__ float Bs[BK][BN + 4];   // [k][n], rows 16B-aligned

    const int bt = blockIdx.z;
    const int m0 = blockIdx.y * BM;
    const int n0 = blockIdx.x * BN;
    const float* Xb = X + (size_t)bt * KDIM * NHW;
    float* Ob = out + (size_t)bt * M * NHW;

    const int tid  = threadIdx.x;
    const int lane = tid & 31;
    const int wid  = tid >> 5;
    const int wm   = wid >> 1;   // 0..3
    const int wn   = wid & 1;    // 0..1
    const int t4   = lane & 3;
    const int g8   = lane >> 2;

    float acc[2][4][4];
    #pragma unroll
    for (int a = 0; a < 2; a++)
        #pragma unroll
        for (int b = 0; b < 4; b++)
            #pragma unroll
            for (int c = 0; c < 4; c++) acc[a][b][c] = 0.f;

    const int mrow = tid >> 3, kq = tid & 7;    // A loader mapping
    const int krow = tid >> 4, nq = tid & 15;   // B loader mapping

    for (int k0 = 0; k0 < KDIM; k0 += BK) {
        __syncthreads();
        // Load A tile: W[m0..m0+127][k0..k0+31], stored transposed [k][m]
        #pragma unroll
        for (int r = 0; r < 4; r++) {
            int m = mrow + 32 * r;
            float4 w4 = *(const float4*)(W + (size_t)(m0 + m) * KDIM + k0 + kq * 4);
            As[kq * 4 + 0][m] = __uint_as_float(f2tf(w4.x));
            As[kq * 4 + 1][m] = __uint_as_float(f2tf(w4.y));
            As[kq * 4 + 2][m] = __uint_as_float(f2tf(w4.z));
            As[kq * 4 + 3][m] = __uint_as_float(f2tf(w4.w));
        }
        // Load B tile: X[k0..k0+31][n0..n0+63]
        #pragma unroll
        for (int p = 0; p < 2; p++) {
            int k = krow + 16 * p;
            float4 x4 = *(const float4*)(Xb + (size_t)(k0 + k) * NHW + n0 + nq * 4);
            float* bp = &Bs[k][nq * 4];
            bp[0] = __uint_as_float(f2tf(x4.x));
            bp[1] = __uint_as_float(f2tf(x4.y));
            bp[2] = __uint_as_float(f2tf(x4.z));
            bp[3] = __uint_as_float(f2tf(x4.w));
        }
        __syncthreads();

        #pragma unroll
        for (int kk = 0; kk < 4; kk++) {
            const int kb = kk * 8;
            unsigned a[2][4], bfr[4][2];
            #pragma unroll
            for (int mf = 0; mf < 2; mf++) {
                int m = wm * 32 + mf * 16;
                a[mf][0] = __float_as_uint(As[kb + t4][m + g8]);
                a[mf][1] = __float_as_uint(As[kb + t4][m + g8 + 8]);
                a[mf][2] = __float_as_uint(As[kb + t4 + 4][m + g8]);
                a[mf][3] = __float_as_uint(As[kb + t4 + 4][m + g8 + 8]);
            }
            #pragma unroll
            for (int nf = 0; nf < 4; nf++) {
                int n = wn * 32 + nf * 8;
                bfr[nf][0] = __float_as_uint(Bs[kb + t4][n + g8]);
                bfr[nf][1] = __float_as_uint(Bs[kb + t4 + 4][n + g8]);
            }
            #pragma unroll
            for (int mf = 0; mf < 2; mf++)
                #pragma unroll
                for (int nf = 0; nf < 4; nf++) {
                    asm volatile(
                        "mma.sync.aligned.m16n8k8.row.col.f32.tf32.tf32.f32 "
                        "{%0,%1,%2,%3}, {%4,%5,%6,%7}, {%8,%9}, {%0,%1,%2,%3};\n"
                        : "+f"(acc[mf][nf][0]), "+f"(acc[mf][nf][1]),
                          "+f"(acc[mf][nf][2]), "+f"(acc[mf][nf][3])
                        : "r"(a[mf][0]), "r"(a[mf][1]), "r"(a[mf][2]), "r"(a[mf][3]),
                          "r"(bfr[nf][0]), "r"(bfr[nf][1]));
                }
        }
    }

    // Epilogue: c0=C[g][2t], c1=C[g][2t+1], c2=C[g+8][2t], c3=C[g+8][2t+1]
    #pragma unroll
    for (int mf = 0; mf < 2; mf++) {
        int r0 = m0 + wm * 32 + mf * 16 + g8;
        float bz0 = bias[r0], bz8 = bias[r0 + 8];
        #pragma unroll
        for (int nf = 0; nf < 4; nf++) {
            int c0 = n0 + wn * 32 + nf * 8 + 2 * t4;
            Ob[(size_t)r0 * NHW + c0]           = acc[mf][nf][0] + bz0;
            Ob[(size_t)r0 * NHW + c0 + 1]       = acc[mf][nf][1] + bz0;
            Ob[(size_t)(r0 + 8) * NHW + c0]     = acc[mf][nf][2] + bz8;
            Ob[(size_t)(r0 + 8) * NHW + c0 + 1] = acc[mf][nf][3] + bz8;
        }
    }
}

// Temporal attention: one thread per (b, head, i, hw). T=16, DIM_HEAD=32.
// qkv layout [bt][o][hw], o: q = h*32+d, k = 256+h*32+d, v = 512+h*32+d.
__global__ __launch_bounds__(128) void attn_kernel(
    const float* __restrict__ qkv, const float* __restrict__ rel,
    float* __restrict__ outp)
{
    const int hw   = blockIdx.x * 128 + threadIdx.x;
    const int i    = blockIdx.y;
    const int head = blockIdx.z & 7;
    const int b    = blockIdx.z >> 3;

    const float scale = 0.1767766952966369f;  // 32^-0.5
    const int btq = b * 16;
    const int oq  = head * 32;

    float q[32];
    {
        const float* qp = qkv + (size_t)((btq + i) * 768 + oq) * NHW + hw;
        #pragma unroll
        for (int d = 0; d < 32; d++) q[d] = qp[(size_t)d * NHW] * scale;
    }

    float s[16];
    #pragma unroll
    for (int j = 0; j < 16; j++) {
        const float* kp = qkv + (size_t)((btq + j) * 768 + 256 + oq) * NHW + hw;
        float a = 0.f;
        #pragma unroll
        for (int d = 0; d < 32; d++) a += q[d] * kp[(size_t)d * NHW];
        s[j] = a + rel[(head * 16 + i) * 16 + j];
    }

    float mx = s[0];
    #pragma unroll
    for (int j = 1; j < 16; j++) mx = fmaxf(mx, s[j]);
    float l = 0.f;
    #pragma unroll
    for (int j = 0; j < 16; j++) { s[j] = __expf(s[j] - mx); l += s[j]; }
    const float inv = 1.f / l;

    float o[32];
    #pragma unroll
    for (int d = 0; d < 32; d++) o[d] = 0.f;
    #pragma unroll
    for (int j = 0; j < 16; j++) {
        const float* vp = qkv + (size_t)((btq + j) * 768 + 512 + oq) * NHW + hw;
        const float p = s[j];
        #pragma unroll
        for (int d = 0; d < 32; d++) o[d] += p * vp[(size_t)d * NHW];
    }

    float* op = outp + (size_t)((btq + i) * 256 + oq) * NHW + hw;
    #pragma unroll
    for (int d = 0; d < 32; d++) op[(size_t)d * NHW] = o[d] * inv;
}

extern "C" void kernel_launch(void* const* d_in, const int* in_sizes, int n_in,
                              void* d_out, int out_size)
{
    const float* x     = (const float*)d_in[0];
    const float* rel   = (const float*)d_in[1];
    const float* w_qkv = (const float*)d_in[2];
    const float* b_qkv = (const float*)d_in[3];
    const float* w_out = (const float*)d_in[4];
    const float* b_out = (const float*)d_in[5];
    float* y = (float*)d_out;

    float* qkv = nullptr;
    float* att = nullptr;
    cudaGetSymbolAddress((void**)&qkv, g_qkv);
    cudaGetSymbolAddress((void**)&att, g_att);

    // Stage 1: QKV projection (M=768)
    gemm_tf32_kernel<768><<<dim3(NHW / 64, 768 / 128, NBT), 256>>>(w_qkv, x, b_qkv, qkv);
    // Stage 2: temporal attention
    attn_kernel<<<dim3(NHW / 128, 16, 32), 128>>>(qkv, rel, att);
    // Stage 3: output projection (M=256)
    gemm_tf32_kernel<256><<<dim3(NHW / 64, 256 / 128, NBT), 256>>>(w_out, att, b_out, y);
}

// round 3
// speedup vs baseline: 1.1632x; 1.1632x over previous
#include <cuda_runtime.h>
#include <cuda_fp16.h>
#include <cstdint>
#include <math.h>

#define NHW 1024
#define KDIM 256
#define NBT 64

// ---------------- scratch (device globals: allocation-guard-safe) -------------
// qkv: [bt][hw][768]  (chan-contiguous), att: [bt][hw][256]
__device__ float g_qkv[(size_t)NBT * NHW * 768];   // 192 MB
__device__ float g_att[(size_t)NBT * NHW * 256];   // 64 MB

// ---------------- helpers ------------------------------------------------------
__device__ __forceinline__ uint32_t smem_u32(const void* p) {
    uint32_t a;
    asm("{ .reg .u64 t; cvta.to.shared.u64 t, %1; cvt.u32.u64 %0, t; }" : "=r"(a) : "l"(p));
    return a;
}
__device__ __forceinline__ uint32_t packh2(float lo, float hi) {
    __half2 h = __floats2half2_rn(lo, hi);   // low 16 bits = lo
    return *reinterpret_cast<uint32_t*>(&h);
}
#define STS128(r0, r1, r2, r3, addr) \
    asm volatile("st.shared.v4.b32 [%0], {%1, %2, %3, %4};" :: "r"(addr), "r"(r0), "r"(r1), "r"(r2), "r"(r3) : "memory")
#define LDSM_X4(r0, r1, r2, r3, addr) \
    asm volatile("ldmatrix.sync.aligned.m8n8.x4.shared.b16 {%0,%1,%2,%3}, [%4];" \
                 : "=r"(r0), "=r"(r1), "=r"(r2), "=r"(r3) : "r"(addr))
#define MMA16816(c, a, b0v, b1v) \
    asm volatile("mma.sync.aligned.m16n8k16.row.col.f32.f16.f16.f32 " \
                 "{%0,%1,%2,%3}, {%4,%5,%6,%7}, {%8,%9}, {%0,%1,%2,%3};" \
                 : "+f"((c)[0]), "+f"((c)[1]), "+f"((c)[2]), "+f"((c)[3]) \
                 : "r"((a)[0]), "r"((a)[1]), "r"((a)[2]), "r"((a)[3]), "r"(b0v), "r"(b1v))

// SMEM plan: B resident full-K: 4 chunks x [128 n][128 B (64 fp16 k)] = 64 KB
//            A double buffer:   2 chunks x [128 m][128 B]             = 32 KB
#define CHUNK_B 16384
#define SMEM_B_OFF 0
#define SMEM_A_OFF (4 * CHUNK_B)
#define SMEM_BYTES (6 * CHUNK_B)
#define SMEM_ALLOC (SMEM_BYTES + 1024)

// row-swizzled byte column: c16 is 16B-aligned column, row&7 selects XOR phase
__device__ __forceinline__ uint32_t swz(uint32_t row, uint32_t c) {
    return row * 128u + (c ^ ((row & 7u) << 4));
}

// C[bt][m][n] = sum_k W[m][k] * X_bt[k][n] + bias[m]
// MODE 0: X stored [bt][k][n] (stage 1), output transposed -> out[bt][n][M]
// MODE 1: X stored [bt][n][k] (stage 3), output normal     -> out[bt][m][NHW]
template<int M, int MODE>
__global__ __launch_bounds__(256, 2) void gemm_hmma_kernel(
    const float* __restrict__ W, const float* __restrict__ X,
    const float* __restrict__ bias, float* __restrict__ out)
{
    extern __shared__ char smem_raw[];
    char* smem = (char*)(((uintptr_t)smem_raw + 1023) & ~(uintptr_t)1023);
    const uint32_t sb = smem_u32(smem);

    const int tid  = threadIdx.x;
    const int lane = tid & 31;
    const int wid  = tid >> 5;
    const int wm   = wid >> 2;             // 0..1  (m dim, 64 rows each)
    const int wn   = wid & 3;              // 0..3  (n dim, 32 cols each)
    const int g8   = lane >> 2;
    const int t4   = lane & 3;

    const int bt = blockIdx.y;
    const int n0 = blockIdx.x * 128;

    const float* Xb = (MODE == 0) ? (X + (size_t)bt * KDIM * NHW)
                                  : (X + (size_t)bt * NHW * KDIM);
    float* Ob = (MODE == 0) ? (out + (size_t)bt * NHW * M)
                            : (out + (size_t)bt * M * NHW);

    // ---- stage B: full K, fp16, layout [chunk][n 0..127][k 64 halves] swizzled
    if (MODE == 0) {
        // X[k][n] -> transpose: per item (kc, kg, ng): lane = n within 32
        #pragma unroll
        for (int kc = 0; kc < 4; kc++) {
            #pragma unroll
            for (int r = 0; r < 4; r++) {
                const int it = r * 8 + wid;          // 0..31
                const int kg = it >> 2;              // 0..7
                const int n  = (it & 3) * 32 + lane; // 0..127
                const float* xp = Xb + (size_t)(kc * 64 + kg * 8) * NHW + n0 + n;
                float v0 = xp[0],         v1 = xp[NHW],     v2 = xp[2 * NHW], v3 = xp[3 * NHW];
                float v4 = xp[4 * NHW],   v5 = xp[5 * NHW], v6 = xp[6 * NHW], v7 = xp[7 * NHW];
                const uint32_t addr = sb + SMEM_B_OFF + kc * CHUNK_B + swz(n, kg * 16u);
                STS128(packh2(v0, v1), packh2(v2, v3), packh2(v4, v5), packh2(v6, v7), addr);
            }
        }
    } else {
        // X[n][k] -> direct vector copy: item (n, q): 16 floats
        #pragma unroll
        for (int kc = 0; kc < 4; kc++) {
            #pragma unroll
            for (int r = 0; r < 2; r++) {
                const int it = r * 256 + tid;
                const int q  = it & 3;
                const int n  = it >> 2;
                const float4* ap = (const float4*)(Xb + (size_t)(n0 + n) * KDIM + kc * 64 + q * 16);
                float4 f0 = ap[0], f1 = ap[1], f2 = ap[2], f3 = ap[3];
                const uint32_t base = sb + SMEM_B_OFF + kc * CHUNK_B;
                STS128(packh2(f0.x, f0.y), packh2(f0.z, f0.w), packh2(f1.x, f1.y), packh2(f1.z, f1.w),
                       base + swz(n, q * 32u));
                STS128(packh2(f2.x, f2.y), packh2(f2.z, f2.w), packh2(f3.x, f3.y), packh2(f3.z, f3.w),
                       base + swz(n, q * 32u + 16u));
            }
        }
    }
    __syncthreads();

    // ldmatrix per-lane geometry
    const int am  = ((lane >> 3) & 1) * 8 + (lane & 7);     // A row within 16
    const uint32_t aC  = ((lane >> 4) & 1) * 16;            // A k-byte sub-col
    const uint32_t aS  = (uint32_t)(am & 7) << 4;
    const int bnl = ((lane >> 4) & 1) * 8 + (lane & 7);     // B row within 16
    const uint32_t bC  = ((lane >> 3) & 1) * 16;
    const uint32_t bS  = (uint32_t)(lane & 7) << 4;

    // A staging geometry (items: it = r*256+tid; kg = it&7, m = it>>3)
    const int s_kg = tid & 7;
    const int s_m0 = tid >> 3;      // +32*r

    for (int mt = 0; mt < M / 128; mt++) {
        const int m0 = mt * 128;

        float acc[4][4][4];
        #pragma unroll
        for (int i = 0; i < 4; i++)
            #pragma unroll
            for (int j = 0; j < 4; j++)
                #pragma unroll
                for (int c = 0; c < 4; c++) acc[i][j][c] = 0.f;

        // prefetch A chunk 0 into regs, store to buf0
        uint32_t pf[4][4];
        {
            #pragma unroll
            for (int r = 0; r < 4; r++) {
                const int m = s_m0 + 32 * r;
                const float4* wp = (const float4*)(W + (size_t)(m0 + m) * KDIM + s_kg * 8);
                float4 f0 = wp[0], f1 = wp[1];
                pf[r][0] = packh2(f0.x, f0.y); pf[r][1] = packh2(f0.z, f0.w);
                pf[r][2] = packh2(f1.x, f1.y); pf[r][3] = packh2(f1.z, f1.w);
            }
            #pragma unroll
            for (int r = 0; r < 4; r++) {
                const int m = s_m0 + 32 * r;
                STS128(pf[r][0], pf[r][1], pf[r][2], pf[r][3],
                       sb + SMEM_A_OFF + swz((uint32_t)m, (uint32_t)s_kg * 16u));
            }
        }

        #pragma unroll
        for (int kc = 0; kc < 4; kc++) {
            if (kc < 3) {   // prefetch next chunk
                #pragma unroll
                for (int r = 0; r < 4; r++) {
                    const int m = s_m0 + 32 * r;
                    const float4* wp = (const float4*)(W + (size_t)(m0 + m) * KDIM + (kc + 1) * 64 + s_kg * 8);
                    float4 f0 = wp[0], f1 = wp[1];
                    pf[r][0] = packh2(f0.x, f0.y); pf[r][1] = packh2(f0.z, f0.w);
                    pf[r][2] = packh2(f1.x, f1.y); pf[r][3] = packh2(f1.z, f1.w);
                }
            }
            __syncthreads();   // A buf[kc&1] visible; prev buf free for STS below

            const uint32_t abase = sb + SMEM_A_OFF + (kc & 1) * CHUNK_B;
            const uint32_t bbase = sb + SMEM_B_OFF + kc * CHUNK_B;
            #pragma unroll
            for (int kk = 0; kk < 4; kk++) {
                const uint32_t ac = ((uint32_t)(kk * 32) + aC) ^ aS;
                const uint32_t bc = ((uint32_t)(kk * 32) + bC) ^ bS;
                uint32_t a[4][4];
                #pragma unroll
                for (int mf = 0; mf < 4; mf++) {
                    const uint32_t addr = abase + (uint32_t)(wm * 64 + mf * 16 + am) * 128u + ac;
                    LDSM_X4(a[mf][0], a[mf][1], a[mf][2], a[mf][3], addr);
                }
                uint32_t b[2][4];
                #pragma unroll
                for (int nfp = 0; nfp < 2; nfp++) {
                    const uint32_t addr = bbase + (uint32_t)(wn * 32 + nfp * 16 + bnl) * 128u + bc;
                    LDSM_X4(b[nfp][0], b[nfp][1], b[nfp][2], b[nfp][3], addr);
                }
                #pragma unroll
                for (int mf = 0; mf < 4; mf++)
                    #pragma unroll
                    for (int nf = 0; nf < 4; nf++)
                        MMA16816(acc[mf][nf], a[mf], b[nf >> 1][(nf & 1) * 2], b[nf >> 1][(nf & 1) * 2 + 1]);
            }

            if (kc < 3) {
                const uint32_t nbase = sb + SMEM_A_OFF + ((kc + 1) & 1) * CHUNK_B;
                #pragma unroll
                for (int r = 0; r < 4; r++) {
                    const int m = s_m0 + 32 * r;
                    STS128(pf[r][0], pf[r][1], pf[r][2], pf[r][3],
                           nbase + swz((uint32_t)m, (uint32_t)s_kg * 16u));
                }
            }
        }

        // ---- epilogue: direct STG (full 32B sectors per lane-quad) ----
        #pragma unroll
        for (int mf = 0; mf < 4; mf++) {
            const int m = m0 + wm * 64 + mf * 16 + g8;
            const float bz0 = bias[m], bz1 = bias[m + 8];
            #pragma unroll
            for (int nf = 0; nf < 4; nf++) {
                const int n = n0 + wn * 32 + nf * 8 + 2 * t4;
                if (MODE == 0) {   // out[n][M] transposed
                    float* p0 = Ob + (size_t)n * M + m;
                    float* p1 = Ob + (size_t)(n + 1) * M + m;
                    p0[0] = acc[mf][nf][0] + bz0;
                    p1[0] = acc[mf][nf][1] + bz0;
                    p0[8] = acc[mf][nf][2] + bz1;
                    p1[8] = acc[mf][nf][3] + bz1;
                } else {           // out[m][NHW]
                    float2 lo = make_float2(acc[mf][nf][0] + bz0, acc[mf][nf][1] + bz0);
                    float2 hi = make_float2(acc[mf][nf][2] + bz1, acc[mf][nf][3] + bz1);
                    *(float2*)(Ob + (size_t)m * NHW + n) = lo;
                    *(float2*)(Ob + (size_t)(m + 8) * NHW + n) = hi;
                }
            }
        }
        // next m-tile's first STS targets buf0 (last read at kc==2, fenced by kc==3's sync)
    }
}

// ---------------- temporal attention, chan-contiguous layout -------------------
// qkv[bt][hw][768]: q at c = h*32+d, k at 256+h*32+d, v at 512+h*32+d
// att[bt][hw][256]: o at c = h*32+d
__global__ __launch_bounds__(128) void attn_kernel(
    const float* __restrict__ qkv, const float* __restrict__ rel,
    float* __restrict__ outp)
{
    const int hw   = blockIdx.x * 128 + threadIdx.x;
    const int i    = blockIdx.y;
    const int head = blockIdx.z & 7;
    const int b    = blockIdx.z >> 3;

    const float scale = 0.1767766952966369f;  // 32^-0.5
    const int bt0 = b * 16;

    float q[32];
    {
        const float4* qp = (const float4*)(qkv + ((size_t)(bt0 + i) * NHW + hw) * 768 + head * 32);
        #pragma unroll
        for (int d4 = 0; d4 < 8; d4++) {
            float4 f = qp[d4];
            q[d4 * 4 + 0] = f.x * scale; q[d4 * 4 + 1] = f.y * scale;
            q[d4 * 4 + 2] = f.z * scale; q[d4 * 4 + 3] = f.w * scale;
        }
    }

    float s[16];
    #pragma unroll
    for (int j = 0; j < 16; j++) {
        const float4* kp = (const float4*)(qkv + ((size_t)(bt0 + j) * NHW + hw) * 768 + 256 + head * 32);
        float a = 0.f;
        #pragma unroll
        for (int d4 = 0; d4 < 8; d4++) {
            float4 f = kp[d4];
            a += q[d4 * 4 + 0] * f.x + q[d4 * 4 + 1] * f.y
               + q[d4 * 4 + 2] * f.z + q[d4 * 4 + 3] * f.w;
        }
        s[j] = a + rel[(head * 16 + i) * 16 + j];
    }

    float mx = s[0];
    #pragma unroll
    for (int j = 1; j < 16; j++) mx = fmaxf(mx, s[j]);
    float l = 0.f;
    #pragma unroll
    for (int j = 0; j < 16; j++) { s[j] = __expf(s[j] - mx); l += s[j]; }
    const float inv = 1.f / l;

    float o[32];
    #pragma unroll
    for (int d = 0; d < 32; d++) o[d] = 0.f;
    #pragma unroll
    for (int j = 0; j < 16; j++) {
        const float4* vp = (const float4*)(qkv + ((size_t)(bt0 + j) * NHW + hw) * 768 + 512 + head * 32);
        const float p = s[j];
        #pragma unroll
        for (int d4 = 0; d4 < 8; d4++) {
            float4 f = vp[d4];
            o[d4 * 4 + 0] += p * f.x; o[d4 * 4 + 1] += p * f.y;
            o[d4 * 4 + 2] += p * f.z; o[d4 * 4 + 3] += p * f.w;
        }
    }

    float4* op = (float4*)(outp + ((size_t)(bt0 + i) * NHW + hw) * 256 + head * 32);
    #pragma unroll
    for (int d4 = 0; d4 < 8; d4++)
        op[d4] = make_float4(o[d4 * 4 + 0] * inv, o[d4 * 4 + 1] * inv,
                             o[d4 * 4 + 2] * inv, o[d4 * 4 + 3] * inv);
}

extern "C" void kernel_launch(void* const* d_in, const int* in_sizes, int n_in,
                              void* d_out, int out_size)
{
    const float* x     = (const float*)d_in[0];
    const float* rel   = (const float*)d_in[1];
    const float* w_qkv = (const float*)d_in[2];
    const float* b_qkv = (const float*)d_in[3];
    const float* w_out = (const float*)d_in[4];
    const float* b_out = (const float*)d_in[5];
    float* y = (float*)d_out;

    float* qkv = nullptr;
    float* att = nullptr;
    cudaGetSymbolAddress((void**)&qkv, g_qkv);
    cudaGetSymbolAddress((void**)&att, g_att);

    cudaFuncSetAttribute(gemm_hmma_kernel<768, 0>, cudaFuncAttributeMaxDynamicSharedMemorySize, SMEM_ALLOC);
    cudaFuncSetAttribute(gemm_hmma_kernel<256, 1>, cudaFuncAttributeMaxDynamicSharedMemorySize, SMEM_ALLOC);

    // Stage 1: QKV projection, out transposed -> qkv[bt][hw][768]
    gemm_hmma_kernel<768, 0><<<dim3(NHW / 128, NBT), 256, SMEM_ALLOC>>>(w_qkv, x, b_qkv, qkv);
    // Stage 2: temporal attention (chan-contiguous)
    attn_kernel<<<dim3(NHW / 128, 16, 32), 128>>>(qkv, rel, att);
    // Stage 3: output projection, normal out -> y[bt][c][hw]
    gemm_hmma_kernel<256, 1><<<dim3(NHW / 128, NBT), 256, SMEM_ALLOC>>>(w_out, att, b_out, y);
}

// round 4
// speedup vs baseline: 2.8781x; 2.4743x over previous
#include <cuda_runtime.h>
#include <cuda_fp16.h>
#include <cstdint>
#include <math.h>

#define NHW 1024
#define KDIM 256
#define NBT 64

// ---------------- scratch (device globals: allocation-guard-safe) -------------
// qkv: [bt][768][hw] fp16 ; att: [bt][hw][256] fp16 (chan-contiguous)
__device__ __half g_qkv[(size_t)NBT * 768 * NHW];   // 96 MB
__device__ __half g_att[(size_t)NBT * NHW * 256];   // 32 MB

// ---------------- helpers ------------------------------------------------------
__device__ __forceinline__ uint32_t smem_u32(const void* p) {
    uint32_t a;
    asm("{ .reg .u64 t; cvta.to.shared.u64 t, %1; cvt.u32.u64 %0, t; }" : "=r"(a) : "l"(p));
    return a;
}
__device__ __forceinline__ uint32_t packh2(float lo, float hi) {
    __half2 h = __floats2half2_rn(lo, hi);
    return *reinterpret_cast<uint32_t*>(&h);
}
#define STS128(r0, r1, r2, r3, addr) \
    asm volatile("st.shared.v4.b32 [%0], {%1, %2, %3, %4};" :: "r"(addr), "r"(r0), "r"(r1), "r"(r2), "r"(r3) : "memory")
#define LDSM_X4(r0, r1, r2, r3, addr) \
    asm volatile("ldmatrix.sync.aligned.m8n8.x4.shared.b16 {%0,%1,%2,%3}, [%4];" \
                 : "=r"(r0), "=r"(r1), "=r"(r2), "=r"(r3) : "r"(addr))
#define MMA16816(c, a, b0v, b1v) \
    asm volatile("mma.sync.aligned.m16n8k16.row.col.f32.f16.f16.f32 " \
                 "{%0,%1,%2,%3}, {%4,%5,%6,%7}, {%8,%9}, {%0,%1,%2,%3};" \
                 : "+f"((c)[0]), "+f"((c)[1]), "+f"((c)[2]), "+f"((c)[3]) \
                 : "r"((a)[0]), "r"((a)[1]), "r"((a)[2]), "r"((a)[3]), "r"(b0v), "r"(b1v))

#define CHUNK_B 16384
#define SMEM_B_OFF 0
#define SMEM_A_OFF (4 * CHUNK_B)
#define SMEM_BYTES (6 * CHUNK_B)
#define SMEM_ALLOC (SMEM_BYTES + 1024)

__device__ __forceinline__ uint32_t swz(uint32_t row, uint32_t c) {
    return row * 128u + (c ^ ((row & 7u) << 4));
}

// C[bt][m][n] = sum_k W[m][k] * X_bt[k][n] + bias[m]
// MODE 0 (stage 1): X fp32 [bt][k][n]; OUT fp16 [bt][m][n]
// MODE 1 (stage 3): X fp16 [bt][n][k]; OUT fp32 [bt][m][n]
template<int M, int MODE>
__global__ __launch_bounds__(256, 2) void gemm_hmma_kernel(
    const float* __restrict__ W, const void* __restrict__ Xv,
    const float* __restrict__ bias, void* __restrict__ outv)
{
    extern __shared__ char smem_raw[];
    char* smem = (char*)(((uintptr_t)smem_raw + 1023) & ~(uintptr_t)1023);
    const uint32_t sb = smem_u32(smem);

    const int tid  = threadIdx.x;
    const int lane = tid & 31;
    const int wid  = tid >> 5;
    const int wm   = wid >> 2;
    const int wn   = wid & 3;
    const int g8   = lane >> 2;
    const int t4   = lane & 3;

    const int bt = blockIdx.y;
    const int n0 = blockIdx.x * 128;

    // ---- stage B: full K resident, fp16, [chunk][n][64 k-halves] swizzled ----
    if (MODE == 0) {
        const float* Xb = (const float*)Xv + (size_t)bt * KDIM * NHW;
        #pragma unroll
        for (int kc = 0; kc < 4; kc++) {
            #pragma unroll
            for (int r = 0; r < 4; r++) {
                const int it = r * 8 + wid;
                const int kg = it >> 2;
                const int n  = (it & 3) * 32 + lane;
                const float* xp = Xb + (size_t)(kc * 64 + kg * 8) * NHW + n0 + n;
                float v0 = xp[0],       v1 = xp[NHW],     v2 = xp[2 * NHW], v3 = xp[3 * NHW];
                float v4 = xp[4 * NHW], v5 = xp[5 * NHW], v6 = xp[6 * NHW], v7 = xp[7 * NHW];
                STS128(packh2(v0, v1), packh2(v2, v3), packh2(v4, v5), packh2(v6, v7),
                       sb + SMEM_B_OFF + kc * CHUNK_B + swz(n, kg * 16u));
            }
        }
    } else {
        const __half* Xb = (const __half*)Xv + (size_t)bt * NHW * KDIM;
        #pragma unroll
        for (int kc = 0; kc < 4; kc++) {
            #pragma unroll
            for (int r = 0; r < 4; r++) {
                const int it = r * 256 + tid;     // 0..1023
                const int n  = it >> 3, q8 = it & 7;
                uint4 v = *(const uint4*)(Xb + (size_t)(n0 + n) * KDIM + kc * 64 + q8 * 8);
                STS128(v.x, v.y, v.z, v.w,
                       sb + SMEM_B_OFF + kc * CHUNK_B + swz((uint32_t)n, (uint32_t)q8 * 16u));
            }
        }
    }
    __syncthreads();

    // ldmatrix per-lane geometry
    const int am  = ((lane >> 3) & 1) * 8 + (lane & 7);
    const uint32_t aC = ((lane >> 4) & 1) * 16;
    const uint32_t aS = (uint32_t)(am & 7) << 4;
    const int bnl = ((lane >> 4) & 1) * 8 + (lane & 7);
    const uint32_t bC = ((lane >> 3) & 1) * 16;
    const uint32_t bS = (uint32_t)(lane & 7) << 4;

    const int s_kg = tid & 7;
    const int s_m0 = tid >> 3;

    for (int mt = 0; mt < M / 128; mt++) {
        const int m0 = mt * 128;

        float acc[4][4][4];
        #pragma unroll
        for (int i = 0; i < 4; i++)
            #pragma unroll
            for (int j = 0; j < 4; j++)
                #pragma unroll
                for (int c = 0; c < 4; c++) acc[i][j][c] = 0.f;

        uint32_t pf[4][4];
        {
            #pragma unroll
            for (int r = 0; r < 4; r++) {
                const int m = s_m0 + 32 * r;
                const float4* wp = (const float4*)(W + (size_t)(m0 + m) * KDIM + s_kg * 8);
                float4 f0 = wp[0], f1 = wp[1];
                pf[r][0] = packh2(f0.x, f0.y); pf[r][1] = packh2(f0.z, f0.w);
                pf[r][2] = packh2(f1.x, f1.y); pf[r][3] = packh2(f1.z, f1.w);
            }
            #pragma unroll
            for (int r = 0; r < 4; r++)
                STS128(pf[r][0], pf[r][1], pf[r][2], pf[r][3],
                       sb + SMEM_A_OFF + swz((uint32_t)(s_m0 + 32 * r), (uint32_t)s_kg * 16u));
        }

        #pragma unroll
        for (int kc = 0; kc < 4; kc++) {
            if (kc < 3) {
                #pragma unroll
                for (int r = 0; r < 4; r++) {
                    const int m = s_m0 + 32 * r;
                    const float4* wp = (const float4*)(W + (size_t)(m0 + m) * KDIM + (kc + 1) * 64 + s_kg * 8);
                    float4 f0 = wp[0], f1 = wp[1];
                    pf[r][0] = packh2(f0.x, f0.y); pf[r][1] = packh2(f0.z, f0.w);
                    pf[r][2] = packh2(f1.x, f1.y); pf[r][3] = packh2(f1.z, f1.w);
                }
            }
            __syncthreads();

            const uint32_t abase = sb + SMEM_A_OFF + (kc & 1) * CHUNK_B;
            const uint32_t bbase = sb + SMEM_B_OFF + kc * CHUNK_B;
            #pragma unroll
            for (int kk = 0; kk < 4; kk++) {
                const uint32_t ac = ((uint32_t)(kk * 32) + aC) ^ aS;
                const uint32_t bc = ((uint32_t)(kk * 32) + bC) ^ bS;
                uint32_t a[4][4];
                #pragma unroll
                for (int mf = 0; mf < 4; mf++)
                    LDSM_X4(a[mf][0], a[mf][1], a[mf][2], a[mf][3],
                            abase + (uint32_t)(wm * 64 + mf * 16 + am) * 128u + ac);
                uint32_t b[2][4];
                #pragma unroll
                for (int nfp = 0; nfp < 2; nfp++)
                    LDSM_X4(b[nfp][0], b[nfp][1], b[nfp][2], b[nfp][3],
                            bbase + (uint32_t)(wn * 32 + nfp * 16 + bnl) * 128u + bc);
                #pragma unroll
                for (int mf = 0; mf < 4; mf++)
                    #pragma unroll
                    for (int nf = 0; nf < 4; nf++)
                        MMA16816(acc[mf][nf], a[mf], b[nf >> 1][(nf & 1) * 2], b[nf >> 1][(nf & 1) * 2 + 1]);
            }

            if (kc < 3) {
                const uint32_t nbase = sb + SMEM_A_OFF + ((kc + 1) & 1) * CHUNK_B;
                #pragma unroll
                for (int r = 0; r < 4; r++)
                    STS128(pf[r][0], pf[r][1], pf[r][2], pf[r][3],
                           nbase + swz((uint32_t)(s_m0 + 32 * r), (uint32_t)s_kg * 16u));
            }
        }

        // ---- epilogue ----
        #pragma unroll
        for (int mf = 0; mf < 4; mf++) {
            const int m = m0 + wm * 64 + mf * 16 + g8;
            const float bz0 = bias[m], bz1 = bias[m + 8];
            #pragma unroll
            for (int nf = 0; nf < 4; nf++) {
                const int n = n0 + wn * 32 + nf * 8 + 2 * t4;
                if (MODE == 0) {
                    __half* Oh = (__half*)outv + (size_t)bt * M * NHW;
                    *(__half2*)(Oh + (size_t)m * NHW + n) =
                        __floats2half2_rn(acc[mf][nf][0] + bz0, acc[mf][nf][1] + bz0);
                    *(__half2*)(Oh + (size_t)(m + 8) * NHW + n) =
                        __floats2half2_rn(acc[mf][nf][2] + bz1, acc[mf][nf][3] + bz1);
                } else {
                    float* Of = (float*)outv + (size_t)bt * M * NHW;
                    *(float2*)(Of + (size_t)m * NHW + n) =
                        make_float2(acc[mf][nf][0] + bz0, acc[mf][nf][1] + bz0);
                    *(float2*)(Of + (size_t)(m + 8) * NHW + n) =
                        make_float2(acc[mf][nf][2] + bz1, acc[mf][nf][3] + bz1);
                }
            }
        }
    }
}

// ---------------- temporal attention: smem K/V tile ----------------------------
// qkv fp16 [bt][768][hw]; att fp16 [bt][hw][256]
// block = (hw-tile of 16, head, b); thread = (i 0..15, hw-pair 0..7)
#define ATT_HW 16
__global__ __launch_bounds__(128) void attn_kernel(
    const __half* __restrict__ qkv, const float* __restrict__ rel,
    __half* __restrict__ att)
{
    __shared__ __half ks[16 * 32 * ATT_HW];
    __shared__ __half vs[16 * 32 * ATT_HW];

    const int tid  = threadIdx.x;
    const int hw0  = blockIdx.x * ATT_HW;
    const int head = blockIdx.y;
    const int b    = blockIdx.z;
    const int bt0  = b * 16;

    // stage K and V tiles (each element read from gmem exactly once)
    const __half* kb = qkv + ((size_t)bt0 * 768 + 256 + head * 32) * NHW + hw0;
    const __half* vb = kb + (size_t)256 * NHW;
    for (int u = tid; u < 1024; u += 128) {
        const int j = u >> 6, d = (u >> 1) & 31, h8 = (u & 1) * 8;
        const size_t g = ((size_t)j * 768 + d) * NHW + h8;
        *(uint4*)&ks[(j * 32 + d) * ATT_HW + h8] = *(const uint4*)&kb[g];
        *(uint4*)&vs[(j * 32 + d) * ATT_HW + h8] = *(const uint4*)&vb[g];
    }
    __syncthreads();

    const int i  = tid >> 3;
    const int pr = tid & 7;
    const float scale = 0.1767766952966369f;  // 32^-0.5

    // q (2 hw positions per thread)
    const __half* qb = qkv + ((size_t)(bt0 + i) * 768 + head * 32) * NHW + hw0 + 2 * pr;
    float2 qf[32];
    #pragma unroll
    for (int d = 0; d < 32; d++) {
        float2 f = __half22float2(*(const __half2*)&qb[(size_t)d * NHW]);
        qf[d] = make_float2(f.x * scale, f.y * scale);
    }

    float s0[16], s1[16];
    #pragma unroll
    for (int j = 0; j < 16; j++) {
        float a0 = 0.f, a1 = 0.f;
        #pragma unroll
        for (int d = 0; d < 32; d++) {
            float2 kf = __half22float2(*(const __half2*)&ks[(j * 32 + d) * ATT_HW + 2 * pr]);
            a0 += qf[d].x * kf.x;
            a1 += qf[d].y * kf.y;
        }
        const float r = rel[(head * 16 + i) * 16 + j];
        s0[j] = a0 + r; s1[j] = a1 + r;
    }

    float m0 = s0[0], m1 = s1[0];
    #pragma unroll
    for (int j = 1; j < 16; j++) { m0 = fmaxf(m0, s0[j]); m1 = fmaxf(m1, s1[j]); }
    float l0 = 0.f, l1 = 0.f;
    #pragma unroll
    for (int j = 0; j < 16; j++) {
        s0[j] = __expf(s0[j] - m0); l0 += s0[j];
        s1[j] = __expf(s1[j] - m1); l1 += s1[j];
    }
    const float inv0 = 1.f / l0, inv1 = 1.f / l1;
    #pragma unroll
    for (int j = 0; j < 16; j++) { s0[j] *= inv0; s1[j] *= inv1; }

    __half* ob = att + ((size_t)(bt0 + i) * NHW + hw0 + 2 * pr) * 256 + head * 32;
    #pragma unroll
    for (int dh = 0; dh < 2; dh++) {
        float o0[16], o1[16];
        #pragma unroll
        for (int d = 0; d < 16; d++) { o0[d] = 0.f; o1[d] = 0.f; }
        #pragma unroll
        for (int j = 0; j < 16; j++) {
            const float p0 = s0[j], p1 = s1[j];
            #pragma unroll
            for (int d = 0; d < 16; d++) {
                float2 vf = __half22float2(*(const __half2*)&vs[(j * 32 + dh * 16 + d) * ATT_HW + 2 * pr]);
                o0[d] += p0 * vf.x;
                o1[d] += p1 * vf.y;
            }
        }
        uint4 u0, u1;
        u0.x = packh2(o0[0],  o0[1]);  u0.y = packh2(o0[2],  o0[3]);
        u0.z = packh2(o0[4],  o0[5]);  u0.w = packh2(o0[6],  o0[7]);
        u1.x = packh2(o0[8],  o0[9]);  u1.y = packh2(o0[10], o0[11]);
        u1.z = packh2(o0[12], o0[13]); u1.w = packh2(o0[14], o0[15]);
        *(uint4*)(ob + dh * 16)     = u0;
        *(uint4*)(ob + dh * 16 + 8) = u1;
        uint4 w0, w1;
        w0.x = packh2(o1[0],  o1[1]);  w0.y = packh2(o1[2],  o1[3]);
        w0.z = packh2(o1[4],  o1[5]);  w0.w = packh2(o1[6],  o1[7]);
        w1.x = packh2(o1[8],  o1[9]);  w1.y = packh2(o1[10], o1[11]);
        w1.z = packh2(o1[12], o1[13]); w1.w = packh2(o1[14], o1[15]);
        *(uint4*)(ob + 256 + dh * 16)     = w0;
        *(uint4*)(ob + 256 + dh * 16 + 8) = w1;
    }
}

extern "C" void kernel_launch(void* const* d_in, const int* in_sizes, int n_in,
                              void* d_out, int out_size)
{
    const float* x     = (const float*)d_in[0];
    const float* rel   = (const float*)d_in[1];
    const float* w_qkv = (const float*)d_in[2];
    const float* b_qkv = (const float*)d_in[3];
    const float* w_out = (const float*)d_in[4];
    const float* b_out = (const float*)d_in[5];
    float* y = (float*)d_out;

    __half* qkv = nullptr;
    __half* att = nullptr;
    cudaGetSymbolAddress((void**)&qkv, g_qkv);
    cudaGetSymbolAddress((void**)&att, g_att);

    cudaFuncSetAttribute(gemm_hmma_kernel<768, 0>, cudaFuncAttributeMaxDynamicSharedMemorySize, SMEM_ALLOC);
    cudaFuncSetAttribute(gemm_hmma_kernel<256, 1>, cudaFuncAttributeMaxDynamicSharedMemorySize, SMEM_ALLOC);

    // Stage 1: QKV projection -> qkv fp16 [bt][768][hw]
    gemm_hmma_kernel<768, 0><<<dim3(NHW / 128, NBT), 256, SMEM_ALLOC>>>(w_qkv, x, b_qkv, qkv);
    // Stage 2: temporal attention -> att fp16 [bt][hw][256]
    attn_kernel<<<dim3(NHW / ATT_HW, 8, 4), 128>>>(qkv, rel, att);
    // Stage 3: output projection -> y fp32 [bt][256][hw]
    gemm_hmma_kernel<256, 1><<<dim3(NHW / 128, NBT), 256, SMEM_ALLOC>>>(w_out, att, b_out, y);
}

// round 6
// speedup vs baseline: 3.0767x; 1.0690x over previous
#include <cuda_runtime.h>
#include <cuda_fp16.h>
#include <cstdint>
#include <math.h>

#define NHW 1024
#define KDIM 256
#define NBT 64

// ---------------- scratch (device globals: allocation-guard-safe) -------------
__device__ __half g_qkv[(size_t)NBT * 768 * NHW];   // 96 MB  [bt][768][hw]
__device__ __half g_att[(size_t)NBT * NHW * 256];   // 32 MB  [bt][hw][256]
__device__ __half g_xh [(size_t)NBT * KDIM * NHW];  // 32 MB  [bt][k][hw]
__device__ __half g_wh [(size_t)(768 + 256) * KDIM];

// ---------------- helpers ------------------------------------------------------
__device__ __forceinline__ uint32_t smem_u32(const void* p) {
    uint32_t a;
    asm("{ .reg .u64 t; cvta.to.shared.u64 t, %1; cvt.u32.u64 %0, t; }" : "=r"(a) : "l"(p));
    return a;
}
__device__ __forceinline__ uint32_t packh2(float lo, float hi) {
    __half2 h = __floats2half2_rn(lo, hi);
    return *reinterpret_cast<uint32_t*>(&h);
}
__device__ __forceinline__ void cpa16(uint32_t dst, const void* src) {
    asm volatile("cp.async.cg.shared.global [%0], [%1], 16;" :: "r"(dst), "l"(src));
}
__device__ __forceinline__ void cpa_commit() { asm volatile("cp.async.commit_group;"); }
template<int N> __device__ __forceinline__ void cpa_wait() {
    asm volatile("cp.async.wait_group %0;" :: "n"(N));
}
#define LDSM_X4(r0, r1, r2, r3, addr) \
    asm volatile("ldmatrix.sync.aligned.m8n8.x4.shared.b16 {%0,%1,%2,%3}, [%4];" \
                 : "=r"(r0), "=r"(r1), "=r"(r2), "=r"(r3) : "r"(addr))
#define LDSM_X4_T(r0, r1, r2, r3, addr) \
    asm volatile("ldmatrix.sync.aligned.m8n8.x4.trans.shared.b16 {%0,%1,%2,%3}, [%4];" \
                 : "=r"(r0), "=r"(r1), "=r"(r2), "=r"(r3) : "r"(addr))
#define MMA16816(c, a, b0v, b1v) \
    asm volatile("mma.sync.aligned.m16n8k16.row.col.f32.f16.f16.f32 " \
                 "{%0,%1,%2,%3}, {%4,%5,%6,%7}, {%8,%9}, {%0,%1,%2,%3};" \
                 : "+f"((c)[0]), "+f"((c)[1]), "+f"((c)[2]), "+f"((c)[3]) \
                 : "r"((a)[0]), "r"((a)[1]), "r"((a)[2]), "r"((a)[3]), "r"(b0v), "r"(b1v))

// ---------------- tiny convert kernels -----------------------------------------
__global__ __launch_bounds__(256) void cvt_x_kernel(const float* __restrict__ x,
                                                    __half* __restrict__ xh) {
    const size_t i = ((size_t)blockIdx.x * 256 + threadIdx.x) * 4;
    float4 f = *(const float4*)(x + i);
    uint2 u;
    u.x = packh2(f.x, f.y); u.y = packh2(f.z, f.w);
    *(uint2*)(xh + i) = u;
}
__global__ __launch_bounds__(256) void cvt_w_kernel(const float* __restrict__ wq,
                                                    const float* __restrict__ wo,
                                                    __half* __restrict__ wh) {
    const size_t i = ((size_t)blockIdx.x * 256 + threadIdx.x) * 4;
    const float* src = (i < (size_t)768 * KDIM) ? (wq + i) : (wo + (i - (size_t)768 * KDIM));
    float4 f = *(const float4*)src;
    uint2 u;
    u.x = packh2(f.x, f.y); u.y = packh2(f.z, f.w);
    *(uint2*)(wh + i) = u;
}

// ---------------- GEMM: cp.async staged, B full-K resident ---------------------
// C[bt][m][n] = sum_k A[m][k] * B_bt[k][n] + bias[m]
// MODE 0: B src = g_xh [bt][k][n]  -> smem [k][n] rows 256B, ldmatrix.trans
//         out fp16 [bt][m][n]
// MODE 1: B src = g_att [bt][n][k] -> smem [n][k] rows 512B, ldmatrix
//         out fp32 [bt][m][n]
#define AST 16384
#define SMEM_B_OFF 0
#define SMEM_A_OFF 65536
#define G_SMEM (65536 + 3 * AST)    // 112 KB

template<int M, int MODE>
__global__ __launch_bounds__(256, 2) void gemm_async_kernel(
    const __half* __restrict__ A, const __half* __restrict__ B,
    const float* __restrict__ bias, void* __restrict__ outv)
{
    extern __shared__ char smem[];
    const uint32_t sb = smem_u32(smem);

    const int tid  = threadIdx.x;
    const int lane = tid & 31;
    const int wid  = tid >> 5;
    const int wm   = wid >> 2;
    const int wn   = wid & 3;
    const int g8   = lane >> 2;
    const int t4   = lane & 3;

    const int bt = blockIdx.y;
    const int n0 = blockIdx.x * 128;

    // ---- staging helpers (per-thread slices) ----
    auto stage_A = [&](int slot, int m0, int kc) {
        const int m   = tid >> 1;
        const int k16b = (tid & 1) * 4;
        const uint32_t dbase = sb + SMEM_A_OFF + slot * AST + (uint32_t)m * 128u;
        const __half* src = A + (size_t)(m0 + m) * KDIM + kc * 64;
        #pragma unroll
        for (int q = 0; q < 4; q++) {
            const int k16 = k16b + q;
            cpa16(dbase + (((uint32_t)k16 * 16u) ^ (((uint32_t)m & 7u) << 4)),
                  src + k16 * 8);
        }
    };

    // ---- prologue: B (full K) + A slots 0..2 ----
    if (MODE == 0) {
        const __half* Bb = B + (size_t)bt * KDIM * NHW;
        const int k = tid;     // 0..255
        const uint32_t dbase = sb + SMEM_B_OFF + (uint32_t)k * 256u;
        const __half* src = Bb + (size_t)k * NHW + n0;
        #pragma unroll
        for (int n16 = 0; n16 < 16; n16++)
            cpa16(dbase + (((uint32_t)n16 * 16u) ^ (((uint32_t)k & 7u) << 4)),
                  src + n16 * 8);
    } else {
        const __half* Bb = B + (size_t)bt * NHW * KDIM;
        const int n = tid >> 1;
        const int kb = (tid & 1) * 16;
        const uint32_t dbase = sb + SMEM_B_OFF + (uint32_t)n * 512u;
        const __half* src = Bb + (size_t)(n0 + n) * KDIM;
        #pragma unroll
        for (int q = 0; q < 16; q++) {
            const int k16 = kb + q;
            cpa16(dbase + (((uint32_t)k16 * 16u) ^ (((uint32_t)n & 7u) << 4)),
                  src + k16 * 8);
        }
    }
    stage_A(0, 0, 0); cpa_commit();
    stage_A(1, 0, 1); cpa_commit();
    stage_A(2, 0, 2); cpa_commit();

    // ldmatrix lane geometry
    const int am  = ((lane >> 3) & 1) * 8 + (lane & 7);
    const uint32_t aC = ((lane >> 4) & 1) * 16;
    const uint32_t aS = (uint32_t)(am & 7) << 4;
    const int bnl = ((lane >> 4) & 1) * 8 + (lane & 7);   // MODE 1
    const uint32_t bC = ((lane >> 3) & 1) * 16;
    const uint32_t bS = (uint32_t)(bnl & 7) << 4;
    const int tk  = lane & 15;                            // MODE 0 (trans)
    const int nc8 = ((lane >> 4) & 1) * 8;
    const uint32_t tS = ((uint32_t)lane & 7u) << 4;

    for (int mt = 0; mt < M / 128; mt++) {
        const int m0 = mt * 128;
        if (mt > 0) {
            __syncthreads();   // slot0 reads (kc=3) done before restage
            stage_A(0, m0, 0); cpa_commit();
            stage_A(1, m0, 1); cpa_commit();
            stage_A(2, m0, 2); cpa_commit();
        }

        float acc[4][4][4];
        #pragma unroll
        for (int i = 0; i < 4; i++)
            #pragma unroll
            for (int j = 0; j < 4; j++)
                #pragma unroll
                for (int c = 0; c < 4; c++) acc[i][j][c] = 0.f;

        #pragma unroll
        for (int kc = 0; kc < 4; kc++) {
            if (kc == 0) cpa_wait<2>();
            else if (kc == 3) cpa_wait<0>();
            else cpa_wait<1>();
            __syncthreads();
            if (kc == 1) { stage_A(0, m0, 3); cpa_commit(); }  // A3 -> slot0

            const uint32_t abase = sb + SMEM_A_OFF + (kc % 3) * AST;
            #pragma unroll
            for (int kk = 0; kk < 4; kk++) {
                uint32_t a[4][4];
                #pragma unroll
                for (int mf = 0; mf < 4; mf++)
                    LDSM_X4(a[mf][0], a[mf][1], a[mf][2], a[mf][3],
                            abase + (uint32_t)(wm * 64 + mf * 16 + am) * 128u
                                  + (((uint32_t)(kk * 32) + aC) ^ aS));
                uint32_t b[2][4];
                #pragma unroll
                for (int nfp = 0; nfp < 2; nfp++) {
                    if (MODE == 0) {
                        const uint32_t addr = sb + SMEM_B_OFF
                            + (uint32_t)(kc * 64 + kk * 16 + tk) * 256u
                            + (((uint32_t)((wn * 32 + nfp * 16 + nc8) * 2)) ^ tS);
                        LDSM_X4_T(b[nfp][0], b[nfp][1], b[nfp][2], b[nfp][3], addr);
                    } else {
                        const uint32_t addr = sb + SMEM_B_OFF
                            + (uint32_t)(wn * 32 + nfp * 16 + bnl) * 512u
                            + (((uint32_t)((kc * 64 + kk * 16) * 2) + bC) ^ bS);
                        LDSM_X4(b[nfp][0], b[nfp][1], b[nfp][2], b[nfp][3], addr);
                    }
                }
                #pragma unroll
                for (int mf = 0; mf < 4; mf++)
                    #pragma unroll
                    for (int nf = 0; nf < 4; nf++)
                        MMA16816(acc[mf][nf], a[mf],
                                 b[nf >> 1][(nf & 1) * 2], b[nf >> 1][(nf & 1) * 2 + 1]);
            }
        }

        // ---- epilogue ----
        #pragma unroll
        for (int mf = 0; mf < 4; mf++) {
            const int m = m0 + wm * 64 + mf * 16 + g8;
            const float bz0 = bias[m], bz1 = bias[m + 8];
            #pragma unroll
            for (int nf = 0; nf < 4; nf++) {
                const int n = n0 + wn * 32 + nf * 8 + 2 * t4;
                if (MODE == 0) {
                    __half* Oh = (__half*)outv + (size_t)bt * M * NHW;
                    *(__half2*)(Oh + (size_t)m * NHW + n) =
                        __floats2half2_rn(acc[mf][nf][0] + bz0, acc[mf][nf][1] + bz0);
                    *(__half2*)(Oh + (size_t)(m + 8) * NHW + n) =
                        __floats2half2_rn(acc[mf][nf][2] + bz1, acc[mf][nf][3] + bz1);
                } else {
                    float* Of = (float*)outv + (size_t)bt * M * NHW;
                    *(float2*)(Of + (size_t)m * NHW + n) =
                        make_float2(acc[mf][nf][0] + bz0, acc[mf][nf][1] + bz0);
                    *(float2*)(Of + (size_t)(m + 8) * NHW + n) =
                        make_float2(acc[mf][nf][2] + bz1, acc[mf][nf][3] + bz1);
                }
            }
        }
    }
}

// ---------------- temporal attention: d-contiguous smem ------------------------
// qkv fp16 [bt][768][hw]; att fp16 [bt][hw][256]
// block = (16-hw tile, head, b), 256 threads = (i 0..15, hwl 0..15)
#define AT_STRIDE 40   // halves per (j,hw) row: 80 B -> conflict-optimal LDS.128

__device__ __forceinline__ float dot8(const float* q, uint4 u) {
    const __half2* p = (const __half2*)&u;
    float a = 0.f;
    #pragma unroll
    for (int c = 0; c < 4; c++) {
        float2 f = __half22float2(p[c]);
        a += q[2 * c] * f.x + q[2 * c + 1] * f.y;
    }
    return a;
}
__device__ __forceinline__ void axpy8(float* o, float p, uint4 u) {
    const __half2* v = (const __half2*)&u;
    #pragma unroll
    for (int c = 0; c < 4; c++) {
        float2 f = __half22float2(v[c]);
        o[2 * c] += p * f.x; o[2 * c + 1] += p * f.y;
    }
}

__global__ __launch_bounds__(256, 2) void attn_kernel(
    const __half* __restrict__ qkv, const float* __restrict__ rel,
    __half* __restrict__ att)
{
    __shared__ __half ks[16 * 16 * AT_STRIDE];
    __shared__ __half vs[16 * 16 * AT_STRIDE];

    const int tid  = threadIdx.x;
    const int hw0  = blockIdx.x * 16;
    const int head = blockIdx.y;
    const int b    = blockIdx.z;
    const int bt0  = b * 16;

    // stage K/V, transposing to [j][hw][d] (d contiguous)
    #pragma unroll
    for (int q = 0; q < 2; q++) {
        const int item = tid * 2 + q;            // 0..511
        const int j  = item >> 5;
        const int dp = (item >> 1) & 15;
        const int h8 = (item & 1) << 3;
        const __half* kp = qkv + ((size_t)(bt0 + j) * 768 + 256 + head * 32 + 2 * dp) * NHW + hw0 + h8;
        uint4 klo = *(const uint4*)kp;
        uint4 khi = *(const uint4*)(kp + NHW);
        uint4 vlo = *(const uint4*)(kp + (size_t)256 * NHW);
        uint4 vhi = *(const uint4*)(kp + (size_t)257 * NHW);
        const __half* kl = (const __half*)&klo; const __half* kh = (const __half*)&khi;
        const __half* vl = (const __half*)&vlo; const __half* vh = (const __half*)&vhi;
        #pragma unroll
        for (int t = 0; t < 8; t++) {
            const int row = (j * 16 + h8 + t) * AT_STRIDE;
            *(__half2*)&ks[row + 2 * dp] = __halves2half2(kl[t], kh[t]);
            *(__half2*)&vs[row + 2 * dp] = __halves2half2(vl[t], vh[t]);
        }
    }
    __syncthreads();

    const int i   = tid >> 4;
    const int hwl = tid & 15;
    const float scale = 0.1767766952966369f;   // 32^-0.5

    float qv[32];
    {
        const __half* qb = qkv + ((size_t)(bt0 + i) * 768 + head * 32) * NHW + hw0 + hwl;
        #pragma unroll
        for (int d = 0; d < 32; d++) qv[d] = __half2float(qb[(size_t)d * NHW]) * scale;
    }

    float s[16];
    #pragma unroll
    for (int j = 0; j < 16; j++) {
        const uint4* kr = (const uint4*)&ks[(j * 16 + hwl) * AT_STRIDE];
        uint4 u0 = kr[0], u1 = kr[1], u2 = kr[2], u3 = kr[3];
        s[j] = dot8(qv, u0) + dot8(qv + 8, u1) + dot8(qv + 16, u2) + dot8(qv + 24, u3)
             + rel[(head * 16 + i) * 16 + j];
    }

    float mx = s[0];
    #pragma unroll
    for (int j = 1; j < 16; j++) mx = fmaxf(mx, s[j]);
    float l = 0.f;
    #pragma unroll
    for (int j = 0; j < 16; j++) { s[j] = __expf(s[j] - mx); l += s[j]; }
    const float inv = 1.f / l;
    #pragma unroll
    for (int j = 0; j < 16; j++) s[j] *= inv;

    __half* ob = att + ((size_t)(bt0 + i) * NHW + hw0 + hwl) * 256 + head * 32;
    #pragma unroll
    for (int dh = 0; dh < 2; dh++) {
        float o[16];
        #pragma unroll
        for (int d = 0; d < 16; d++) o[d] = 0.f;
        #pragma unroll
        for (int j = 0; j < 16; j++) {
            const uint4* vr = (const uint4*)&vs[(j * 16 + hwl) * AT_STRIDE + dh * 16];
            uint4 u0 = vr[0], u1 = vr[1];
            axpy8(o, s[j], u0);
            axpy8(o + 8, s[j], u1);
        }
        uint4 r0, r1;
        r0.x = packh2(o[0],  o[1]);  r0.y = packh2(o[2],  o[3]);
        r0.z = packh2(o[4],  o[5]);  r0.w = packh2(o[6],  o[7]);
        r1.x = packh2(o[8],  o[9]);  r1.y = packh2(o[10], o[11]);
        r1.z = packh2(o[12], o[13]); r1.w = packh2(o[14], o[15]);
        *(uint4*)(ob + dh * 16)     = r0;
        *(uint4*)(ob + dh * 16 + 8) = r1;
    }
}

extern "C" void kernel_launch(void* const* d_in, const int* in_sizes, int n_in,
                              void* d_out, int out_size)
{
    const float* x     = (const float*)d_in[0];
    const float* rel   = (const float*)d_in[1];
    const float* w_qkv = (const float*)d_in[2];
    const float* b_qkv = (const float*)d_in[3];
    const float* w_out = (const float*)d_in[4];
    const float* b_out = (const float*)d_in[5];
    float* y = (float*)d_out;

    __half *qkv = nullptr, *att = nullptr, *xh = nullptr, *wh = nullptr;
    cudaGetSymbolAddress((void**)&qkv, g_qkv);
    cudaGetSymbolAddress((void**)&att, g_att);
    cudaGetSymbolAddress((void**)&xh,  g_xh);
    cudaGetSymbolAddress((void**)&wh,  g_wh);

    cudaFuncSetAttribute(gemm_async_kernel<768, 0>, cudaFuncAttributeMaxDynamicSharedMemorySize, G_SMEM);
    cudaFuncSetAttribute(gemm_async_kernel<256, 1>, cudaFuncAttributeMaxDynamicSharedMemorySize, G_SMEM);

    // Stage 0: fp16 conversions
    cvt_w_kernel<<<(768 + 256) * KDIM / 1024, 256>>>(w_qkv, w_out, wh);
    cvt_x_kernel<<<(int)((size_t)NBT * KDIM * NHW / 1024), 256>>>(x, xh);
    // Stage 1: QKV projection -> qkv fp16 [bt][768][hw]
    gemm_async_kernel<768, 0><<<dim3(NHW / 128, NBT), 256, G_SMEM>>>(wh, xh, b_qkv, qkv);
    // Stage 2: temporal attention -> att fp16 [bt][hw][256]
    attn_kernel<<<dim3(NHW / 16, 8, 4), 256>>>(qkv, rel, att);
    // Stage 3: output projection -> y fp32 [bt][256][hw]
    gemm_async_kernel<256, 1><<<dim3(NHW / 128, NBT), 256, G_SMEM>>>(
        wh + (size_t)768 * KDIM, att, b_out, y);
}